// round 3
// baseline (speedup 1.0000x reference)
#include <cuda_runtime.h>

// Integrate-and-fire, sequential-equivalent of the reference:
//   per neuron: v=0 at t=0 and t=100; v += x[t]; if (v>2) {spike=1; v=0;}
// in  (4,200,64,64,8):  in[b][t][h1][h2][c],  stride_t=32768
// out (4,200,64,8,64):  out[b][t][h2][c][h1], stride_t=32768
//
// Block = (b, h2, chunk): 512 blocks x 128 threads.
// Loader role:  thread -> (h1 = tid>>1, cg = tid&1), LDG.128 of 4 c-values.
// Scan role:    thread -> (c = tid>>4, h1b = (tid&15)*4), owns 4 consecutive
//               h1 neurons -> LDS.128 from smem, STG.128 to out (contiguous).
// smem layout sm[buf][k][c*68 + h1]: stride 68 => STS conflict-free,
// 16B-aligned for the scan-side LDS.128.

#define T_STRIDE 32768
#define CHUNK    100
#define KT       5
#define NTILES   (CHUNK / KT)   // 20
#define ROWS     68             // padded c-stride in floats

__global__ __launch_bounds__(128)
void iaf_kernel(const float* __restrict__ in, float* __restrict__ out) {
    const int bid   = blockIdx.x;        // 512 = b(4) x h2(64) x chunk(2)
    const int b     = bid >> 7;
    const int h2    = (bid >> 1) & 63;
    const int chunk = bid & 1;
    const int tid   = threadIdx.x;

    // loader mapping
    const int h1_l = tid >> 1;           // 0..63
    const int cg_l = tid & 1;            // 0..1 (float4 group within c)
    // scan mapping
    const int c_s  = tid >> 4;           // 0..7
    const int h1b  = (tid & 15) << 2;    // 0,4,...,60

    __shared__ float sm[2][KT][8 * ROWS];

    const size_t tb = (size_t)(b * 200 + chunk * CHUNK) * T_STRIDE;
    const float* inp  = in  + tb + h1_l * 512 + h2 * 8 + cg_l * 4;
    float*       outp = out + tb + h2 * 512 + c_s * 64 + h1b;
    const int    s_idx = c_s * ROWS + h1b;
    const int    w_idx0 = (4 * cg_l + 0) * ROWS + h1_l;

    // prologue: load tile 0
    float4 r[KT];
    #pragma unroll
    for (int k = 0; k < KT; k++)
        r[k] = *(const float4*)(inp + (size_t)k * T_STRIDE);

    #pragma unroll
    for (int k = 0; k < KT; k++) {
        sm[0][k][w_idx0 + 0 * ROWS] = r[k].x;
        sm[0][k][w_idx0 + 1 * ROWS] = r[k].y;
        sm[0][k][w_idx0 + 2 * ROWS] = r[k].z;
        sm[0][k][w_idx0 + 3 * ROWS] = r[k].w;
    }
    __syncthreads();

    float v0 = 0.f, v1 = 0.f, v2 = 0.f, v3 = 0.f;

    for (int tile = 0; tile < NTILES; tile++) {
        const int cur = tile & 1;

        // issue next tile's global loads early (latency hidden by scan below)
        if (tile + 1 < NTILES) {
            const float* p = inp + (size_t)((tile + 1) * KT) * T_STRIDE;
            #pragma unroll
            for (int k = 0; k < KT; k++)
                r[k] = *(const float4*)(p + (size_t)k * T_STRIDE);
        }

        // scan current tile + coalesced vector stores
        #pragma unroll
        for (int k = 0; k < KT; k++) {
            float4 x = *(const float4*)&sm[cur][k][s_idx];
            v0 += x.x; v1 += x.y; v2 += x.z; v3 += x.w;
            float4 s;
            s.x = (v0 > 2.0f) ? 1.0f : 0.0f;  v0 = (v0 > 2.0f) ? 0.0f : v0;
            s.y = (v1 > 2.0f) ? 1.0f : 0.0f;  v1 = (v1 > 2.0f) ? 0.0f : v1;
            s.z = (v2 > 2.0f) ? 1.0f : 0.0f;  v2 = (v2 > 2.0f) ? 0.0f : v2;
            s.w = (v3 > 2.0f) ? 1.0f : 0.0f;  v3 = (v3 > 2.0f) ? 0.0f : v3;
            *(float4*)(outp + (size_t)(tile * KT + k) * T_STRIDE) = s;
        }

        // stage next tile into the other buffer
        if (tile + 1 < NTILES) {
            #pragma unroll
            for (int k = 0; k < KT; k++) {
                sm[1 - cur][k][w_idx0 + 0 * ROWS] = r[k].x;
                sm[1 - cur][k][w_idx0 + 1 * ROWS] = r[k].y;
                sm[1 - cur][k][w_idx0 + 2 * ROWS] = r[k].z;
                sm[1 - cur][k][w_idx0 + 3 * ROWS] = r[k].w;
            }
        }
        __syncthreads();
    }
}

extern "C" void kernel_launch(void* const* d_in, const int* in_sizes, int n_in,
                              void* d_out, int out_size) {
    const float* in  = (const float*)d_in[0];
    float*       out = (float*)d_out;
    iaf_kernel<<<512, 128>>>(in, out);
}

// round 4
// speedup vs baseline: 1.6447x; 1.6447x over previous
#include <cuda_runtime.h>

// Integrate-and-fire, sequential-equivalent of the reference:
//   per neuron: v=0 at t=0 and t=100; v += x[t]; if (v>2) {spike=1; v=0;}
// in  (4,200,64,64,8):  in[b][t][h1][h2][c],  stride_t=32768
// out (4,200,64,8,64):  out[b][t][h2][c][h1], stride_t=32768
//
// Grid: 512 blocks = (b:4, h2:64, chunk:2), 512 threads/block (1 neuron each).
// Loader:  tid = k*128 + h1*2 + cg  -> LDG.128 of 4 c-values, 4 timesteps
//          per tile loaded in parallel across the k sub-groups.
// Scanner: tid = c*64 + h1          -> LDS.32 conflict-free (stride-68 rows),
//          STG.32 fully coalesced (2KB contiguous per timestep).
// Double-buffered smem, one barrier per 4-timestep tile; next tile's LDG
// issued before the current scan so DRAM reads overlap compute+stores.

#define T_STRIDE 32768
#define CHUNK    100
#define KT       4
#define NTILES   (CHUNK / KT)   // 25
#define ROW      68             // padded c-stride (bank = (4c+h1)%32, conflict-free)

__global__ __launch_bounds__(512)
void iaf_kernel(const float* __restrict__ in, float* __restrict__ out) {
    const int bid   = blockIdx.x;          // 512 = b(4) x h2(64) x chunk(2)
    const int b     = bid >> 7;
    const int h2    = (bid >> 1) & 63;
    const int chunk = bid & 1;
    const int tid   = threadIdx.x;

    // loader mapping
    const int k_l  = tid >> 7;             // 0..3  (timestep within tile)
    const int h1_l = (tid >> 1) & 63;      // 0..63
    const int cg_l = tid & 1;              // 0..1  (float4 group within c)
    // scan mapping
    const int c_s  = tid >> 6;             // 0..7
    const int h1_s = tid & 63;             // 0..63

    __shared__ float sm[2][KT][8 * ROW];

    const size_t tb = (size_t)(b * 200 + chunk * CHUNK) * T_STRIDE;
    const float* inp  = in  + tb + (size_t)k_l * T_STRIDE
                            + h1_l * 512 + h2 * 8 + cg_l * 4;
    float*       outp = out + tb + h2 * 512 + tid;   // c_s*64 + h1_s == tid

    const int w0 = (cg_l * 4) * ROW + h1_l;          // STS base (then +ROW per c)
    const int s0 = c_s * ROW + h1_s;                 // LDS index

    // prologue: tile 0
    float4 r = *(const float4*)inp;
    sm[0][k_l][w0 + 0 * ROW] = r.x;
    sm[0][k_l][w0 + 1 * ROW] = r.y;
    sm[0][k_l][w0 + 2 * ROW] = r.z;
    sm[0][k_l][w0 + 3 * ROW] = r.w;
    __syncthreads();

    float v = 0.0f;

    for (int tile = 0; tile < NTILES; tile++) {
        const int cur = tile & 1;

        // issue next tile's global load early (hidden behind the scan)
        if (tile + 1 < NTILES)
            r = *(const float4*)(inp + (size_t)(tile + 1) * KT * T_STRIDE);

        // sequential membrane scan + coalesced stores
        #pragma unroll
        for (int k = 0; k < KT; k++) {
            v += sm[cur][k][s0];
            float spike = 0.0f;
            if (v > 2.0f) { spike = 1.0f; v = 0.0f; }
            outp[(size_t)(tile * KT + k) * T_STRIDE] = spike;
        }

        // stage next tile into the other buffer
        if (tile + 1 < NTILES) {
            sm[1 - cur][k_l][w0 + 0 * ROW] = r.x;
            sm[1 - cur][k_l][w0 + 1 * ROW] = r.y;
            sm[1 - cur][k_l][w0 + 2 * ROW] = r.z;
            sm[1 - cur][k_l][w0 + 3 * ROW] = r.w;
        }
        __syncthreads();
    }
}

extern "C" void kernel_launch(void* const* d_in, const int* in_sizes, int n_in,
                              void* d_out, int out_size) {
    const float* in  = (const float*)d_in[0];
    float*       out = (float*)d_out;
    iaf_kernel<<<512, 512>>>(in, out);
}

// round 5
// speedup vs baseline: 1.8379x; 1.1175x over previous
#include <cuda_runtime.h>

// Integrate-and-fire, sequential-equivalent of the reference:
//   per neuron: v=0 at t=0 and t=100; v += x[t]; if (v>2) {spike=1; v=0;}
// in  (4,200,64,64,8):  in[b][t][h1][h2][c],  stride_t=32768
// out (4,200,64,8,64):  out[b][t][h2][c][h1], stride_t=32768
//
// Grid 512 = (b:4, h2:64, chunk:2), 512 threads.
// Scan role (per-neuron register scan):
//   tid = h1*8 + c  -> coalesced LDG.32 over t (4 prefetched, MLP=4),
//   membrane chain entirely in registers, spikes -> smem (swizzled STS,
//   conflict-free: bank = 4*((w^c)&7) + i).
// Store role:
//   tid = k*128 + c*16 + h1q -> LDS.128 of 4 consecutive h1 (XOR swizzle
//   keeps float4 contiguity: (4*h1q+j)^(4c) = 4*(h1q^c)+j), STG.128,
//   512B contiguous per warp.
// Double-buffered spike smem, one __syncthreads per 4-step tile.

#define T_STRIDE 32768
#define CHUNK    100
#define KT       4
#define NTILES   (CHUNK / KT)   // 25

__global__ __launch_bounds__(512)
void iaf_kernel(const float* __restrict__ in, float* __restrict__ out) {
    const int bid   = blockIdx.x;          // 512 = b(4) x h2(64) x chunk(2)
    const int b     = bid >> 7;
    const int h2    = (bid >> 1) & 63;
    const int chunk = bid & 1;
    const int tid   = threadIdx.x;

    // scan mapping (load-coalesced, one neuron per thread)
    const int h1_s = tid >> 3;             // 0..63
    const int c_s  = tid & 7;              // 0..7
    // store mapping
    const int k_o  = tid >> 7;             // 0..3
    const int c_o  = (tid >> 4) & 7;       // 0..7
    const int h1q  = tid & 15;             // 0..15 (float4 group of h1)

    __shared__ float sm[2][KT * 512];

    const size_t tb = (size_t)(b * 200 + chunk * CHUNK) * T_STRIDE;
    const float* inp  = in  + tb + h1_s * 512 + h2 * 8 + c_s;
    float*       outp = out + tb + (size_t)k_o * T_STRIDE
                            + h2 * 512 + c_o * 64 + h1q * 4;

    // swizzled smem indices
    const int sts_idx = c_s * 64 + (h1_s ^ (c_s << 2));          // scan STS
    const int lds_idx = k_o * 512 + c_o * 64 + ((h1q ^ c_o) << 2); // store LDS.128

    // prologue: load tile 0 into registers
    float x0 = inp[0 * T_STRIDE];
    float x1 = inp[1 * T_STRIDE];
    float x2 = inp[2 * T_STRIDE];
    float x3 = inp[3 * T_STRIDE];

    float v = 0.0f;

    #pragma unroll 1
    for (int tile = 0; tile < NTILES; tile++) {
        const int cur = tile & 1;

        // prefetch next tile (4 independent loads, hidden behind this tile)
        float n0, n1, n2, n3;
        if (tile + 1 < NTILES) {
            const float* p = inp + (size_t)(tile + 1) * KT * T_STRIDE;
            n0 = p[0 * T_STRIDE];
            n1 = p[1 * T_STRIDE];
            n2 = p[2 * T_STRIDE];
            n3 = p[3 * T_STRIDE];
        }

        // register membrane scan; spikes -> swizzled smem
        float s;
        v += x0; s = (v > 2.0f) ? 1.0f : 0.0f; v = (v > 2.0f) ? 0.0f : v;
        sm[cur][0 * 512 + sts_idx] = s;
        v += x1; s = (v > 2.0f) ? 1.0f : 0.0f; v = (v > 2.0f) ? 0.0f : v;
        sm[cur][1 * 512 + sts_idx] = s;
        v += x2; s = (v > 2.0f) ? 1.0f : 0.0f; v = (v > 2.0f) ? 0.0f : v;
        sm[cur][2 * 512 + sts_idx] = s;
        v += x3; s = (v > 2.0f) ? 1.0f : 0.0f; v = (v > 2.0f) ? 0.0f : v;
        sm[cur][3 * 512 + sts_idx] = s;

        __syncthreads();

        // transpose-store: LDS.128 + STG.128 (fully coalesced)
        float4 s4 = *(const float4*)&sm[cur][lds_idx];
        *(float4*)(outp + (size_t)tile * KT * T_STRIDE) = s4;

        x0 = n0; x1 = n1; x2 = n2; x3 = n3;
    }
}

extern "C" void kernel_launch(void* const* d_in, const int* in_sizes, int n_in,
                              void* d_out, int out_size) {
    const float* in  = (const float*)d_in[0];
    float*       out = (float*)d_out;
    iaf_kernel<<<512, 512>>>(in, out);
}

// round 6
// speedup vs baseline: 1.9089x; 1.0386x over previous
#include <cuda_runtime.h>
#include <stdint.h>

// Integrate-and-fire, sequential-equivalent of the reference:
//   per neuron: v=0 at t=0 and t=100; v += x[t]; if (v>2) {spike=1; v=0;}
// in  (4,200,64,64,8):  in[b][t][h1][h2][c],  stride_t=32768
// out (4,200,64,8,64):  out[b][t][h2][c][h1], stride_t=32768
//
// Grid 1024 = (b:4, h2:64, chunk:2, h1-half:2), 256 threads (1 neuron each).
// Scan role: tid=(h1l*8+c) -> coalesced LDG.32 over t, register membrane
//   scan; 8 timesteps packed into two uint32 spike-byte words -> 2 STS.32
//   (swizzle bank=(h1l^4c)%32, conflict-free).
// Store role: tid=(k4*64 + c*8 + h1q) -> LDS.128 of 4 neighboring neurons'
//   packed words, extract byte k4, STG.128 (fully coalesced 128B segments).
// Double-buffered phase pipeline: full next-phase (8 loads) prefetched into
// registers; ONE __syncthreads per 8-step phase (13 total).

#define T_STRIDE 32768

__device__ __forceinline__ float4 unpack4(uint4 a, int sh) {
    float4 f;
    f.x = __uint_as_float(((a.x >> sh) & 1u) * 0x3f800000u);
    f.y = __uint_as_float(((a.y >> sh) & 1u) * 0x3f800000u);
    f.z = __uint_as_float(((a.z >> sh) & 1u) * 0x3f800000u);
    f.w = __uint_as_float(((a.w >> sh) & 1u) * 0x3f800000u);
    return f;
}

#define STEP(W, XV, BIT) do { v += (XV); if (v > 2.0f) { (W) |= (BIT); v = 0.0f; } } while (0)

#define PHASE(CUR, PAR, P) do {                                               \
    uint32_t w0 = 0u, w1 = 0u;                                                \
    STEP(w0, CUR[0], 1u);        STEP(w0, CUR[1], 1u << 8);                   \
    STEP(w0, CUR[2], 1u << 16);  STEP(w0, CUR[3], 1u << 24);                  \
    STEP(w1, CUR[4], 1u);        STEP(w1, CUR[5], 1u << 8);                   \
    STEP(w1, CUR[6], 1u << 16);  STEP(w1, CUR[7], 1u << 24);                  \
    sp[PAR][0][sts] = w0;                                                     \
    sp[PAR][1][sts] = w1;                                                     \
    __syncthreads();                                                          \
    uint4 a0 = *(const uint4*)&sp[PAR][0][lds];                               \
    *(float4*)(outp + (size_t)((P) * 8 + k4) * T_STRIDE) = unpack4(a0, sh);   \
    uint4 a1 = *(const uint4*)&sp[PAR][1][lds];                               \
    *(float4*)(outp + (size_t)((P) * 8 + 4 + k4) * T_STRIDE) = unpack4(a1, sh); \
} while (0)

__global__ __launch_bounds__(256, 6)
void iaf_kernel(const float* __restrict__ in, float* __restrict__ out) {
    const int bid   = blockIdx.x;            // 1024 = b(4) x h2(64) x chunk(2) x half(2)
    const int b     = bid >> 8;
    const int h2    = (bid >> 2) & 63;
    const int chunk = (bid >> 1) & 1;
    const int half  = bid & 1;
    const int tid   = threadIdx.x;

    // scan mapping (load-coalesced)
    const int h1l = tid >> 3;                // 0..31 (local h1 within half)
    const int c_s = tid & 7;                 // 0..7
    // store mapping
    const int k4  = tid >> 6;                // 0..3 (byte / timestep within word)
    const int c_o = (tid >> 3) & 7;          // 0..7
    const int h1q = tid & 7;                 // 0..7 (float4 group within 32 h1)

    __shared__ __align__(16) uint32_t sp[2][2][256];  // [parity][word-plane][c*32 + swz h1]

    const size_t tb = (size_t)(b * 200 + chunk * 100) * T_STRIDE;
    const float* inp  = in  + tb + (half * 32 + h1l) * 512 + h2 * 8 + c_s;
    float*       outp = out + tb + h2 * 512 + c_o * 64 + half * 32 + h1q * 4;

    const int sts = c_s * 32 + (h1l ^ (c_s << 2));        // conflict-free STS
    const int lds = c_o * 32 + ((h1q ^ c_o) << 2);        // 16B-aligned LDS.128
    const int sh  = k4 * 8;

    float x0[8], x1[8];

    // prologue: phase 0 into x0
    #pragma unroll
    for (int k = 0; k < 8; k++) x0[k] = inp[(size_t)k * T_STRIDE];

    float v = 0.0f;

    for (int pp = 0; pp < 6; pp++) {
        const int p0 = 2 * pp;

        // prefetch phase p0+1 -> x1 (always a full 8)
        {
            const float* np = inp + (size_t)(p0 + 1) * (8 * T_STRIDE);
            #pragma unroll
            for (int k = 0; k < 8; k++) x1[k] = np[(size_t)k * T_STRIDE];
        }

        PHASE(x0, 0, p0);

        // prefetch phase p0+2 -> x0 (last iteration: tail = 4 steps only)
        {
            const float* np = inp + (size_t)(p0 + 2) * (8 * T_STRIDE);
            #pragma unroll
            for (int k = 0; k < 8; k++)
                if (k < 4 || pp < 5) x0[k] = np[(size_t)k * T_STRIDE];
        }

        PHASE(x1, 1, p0 + 1);
    }

    // tail: timesteps 96..99 from x0[0..3]
    {
        uint32_t w0 = 0u;
        STEP(w0, x0[0], 1u);        STEP(w0, x0[1], 1u << 8);
        STEP(w0, x0[2], 1u << 16);  STEP(w0, x0[3], 1u << 24);
        sp[0][0][sts] = w0;
        __syncthreads();
        uint4 a0 = *(const uint4*)&sp[0][0][lds];
        *(float4*)(outp + (size_t)(96 + k4) * T_STRIDE) = unpack4(a0, sh);
    }
}

extern "C" void kernel_launch(void* const* d_in, const int* in_sizes, int n_in,
                              void* d_out, int out_size) {
    const float* in  = (const float*)d_in[0];
    float*       out = (float*)d_out;
    iaf_kernel<<<1024, 256>>>(in, out);
}

// round 9
// speedup vs baseline: 2.0081x; 1.0520x over previous
#include <cuda_runtime.h>
#include <stdint.h>

// Integrate-and-fire, sequential-equivalent of the reference:
//   per neuron: v=0 at t=0 and t=100; v += x[t]; if (v>2) {spike=1; v=0;}
// in  (4,200,64,64,8):  in[b][t][h1][h2][c],  stride_t=32768
// out (4,200,64,8,64):  out[b][t][h2][c][h1], stride_t=32768
//
// Grid 512 = (b:4, h2:64, h1-half:2), 256 threads, 1 neuron/thread running
// ALL 200 timesteps (membrane reset at t=100 handled in-register), so the
// whole launch is a SINGLE wave (512 < 148*occ) -- no wave-2 tail.
// 25 exact phases of 8 timesteps:
//   scan role: tid=(h1l*8+c) -> coalesced LDG.32, register membrane scan,
//     8 spikes packed as bytes into two uint32 -> 2 STS.32 (XOR swizzle,
//     conflict-free).
//   store role: tid=(k4*64+c*8+h1q) -> LDS.128 of 4 packed words, extract
//     byte k4, STG.128 fully coalesced.
// Double-buffered register prefetch (16 loads in flight), 1 barrier/phase.

#define T_STRIDE 32768

__device__ __forceinline__ float4 unpack4(uint4 a, int sh) {
    float4 f;
    f.x = __uint_as_float(((a.x >> sh) & 1u) * 0x3f800000u);
    f.y = __uint_as_float(((a.y >> sh) & 1u) * 0x3f800000u);
    f.z = __uint_as_float(((a.z >> sh) & 1u) * 0x3f800000u);
    f.w = __uint_as_float(((a.w >> sh) & 1u) * 0x3f800000u);
    return f;
}

#define STEP(W, XV, BIT) do { v += (XV); if (v > 2.0f) { (W) |= (BIT); v = 0.0f; } } while (0)

// One 8-step phase: pack spikes, stage through smem, transpose-store.
// RESETMID: membrane reset between step 3 and 4 (chunk boundary t=100).
#define PHASE(CUR, PAR, P, RESETMID) do {                                     \
    uint32_t w0 = 0u, w1 = 0u;                                                \
    STEP(w0, CUR[0], 1u);        STEP(w0, CUR[1], 1u << 8);                   \
    STEP(w0, CUR[2], 1u << 16);  STEP(w0, CUR[3], 1u << 24);                  \
    if (RESETMID) v = 0.0f;                                                   \
    STEP(w1, CUR[4], 1u);        STEP(w1, CUR[5], 1u << 8);                   \
    STEP(w1, CUR[6], 1u << 16);  STEP(w1, CUR[7], 1u << 24);                  \
    sp[PAR][0][sts] = w0;                                                     \
    sp[PAR][1][sts] = w1;                                                     \
    __syncthreads();                                                          \
    uint4 a0 = *(const uint4*)&sp[PAR][0][lds];                               \
    *(float4*)(outp + (size_t)((P) * 8 + k4) * T_STRIDE) = unpack4(a0, sh);   \
    uint4 a1 = *(const uint4*)&sp[PAR][1][lds];                               \
    *(float4*)(outp + (size_t)((P) * 8 + 4 + k4) * T_STRIDE) = unpack4(a1, sh); \
} while (0)

__global__ __launch_bounds__(256)
void iaf_kernel(const float* __restrict__ in, float* __restrict__ out) {
    const int bid  = blockIdx.x;             // 512 = b(4) x h2(64) x half(2)
    const int b    = bid >> 7;
    const int h2   = (bid >> 1) & 63;
    const int half = bid & 1;
    const int tid  = threadIdx.x;

    // scan mapping (load-coalesced)
    const int h1l = tid >> 3;                // 0..31 (local h1 within half)
    const int c_s = tid & 7;                 // 0..7
    // store mapping
    const int k4  = tid >> 6;                // 0..3 (byte within packed word)
    const int c_o = (tid >> 3) & 7;          // 0..7
    const int h1q = tid & 7;                 // 0..7 (float4 group within 32 h1)

    __shared__ __align__(16) uint32_t sp[2][2][256];

    const size_t tb = (size_t)b * 200 * T_STRIDE;
    const float* inp  = in  + tb + (half * 32 + h1l) * 512 + h2 * 8 + c_s;
    float*       outp = out + tb + h2 * 512 + c_o * 64 + half * 32 + h1q * 4;

    const int sts = c_s * 32 + (h1l ^ (c_s << 2));     // conflict-free STS
    const int lds = c_o * 32 + ((h1q ^ c_o) << 2);     // 16B-aligned LDS.128
    const int sh  = k4 * 8;

    float x0[8], x1[8];

    // prologue: phase 0 -> x0
    #pragma unroll
    for (int k = 0; k < 8; k++) x0[k] = inp[(size_t)k * T_STRIDE];

    float v = 0.0f;

    // 25 phases = 12 double-iterations + epilogue phase 24.
    // All prefetches inside the loop are unconditional (p0+2 <= 24).
    for (int pp = 0; pp < 12; pp++) {
        const int p0 = 2 * pp;

        {   // prefetch phase p0+1 -> x1
            const float* np = inp + (size_t)(p0 + 1) * (8 * T_STRIDE);
            #pragma unroll
            for (int k = 0; k < 8; k++) x1[k] = np[(size_t)k * T_STRIDE];
        }

        PHASE(x0, 0, p0, p0 == 12);          // t=100 falls mid-phase-12

        {   // prefetch phase p0+2 -> x0
            const float* np = inp + (size_t)(p0 + 2) * (8 * T_STRIDE);
            #pragma unroll
            for (int k = 0; k < 8; k++) x0[k] = np[(size_t)k * T_STRIDE];
        }

        PHASE(x1, 1, p0 + 1, false);         // odd phases never hit t=100
    }

    // epilogue: phase 24 (t=192..199), already in x0
    PHASE(x0, 0, 24, false);
}

extern "C" void kernel_launch(void* const* d_in, const int* in_sizes, int n_in,
                              void* d_out, int out_size) {
    const float* in  = (const float*)d_in[0];
    float*       out = (float*)d_out;
    iaf_kernel<<<512, 256>>>(in, out);
}